// round 7
// baseline (speedup 1.0000x reference)
#include <cuda_runtime.h>

#define LEAK   0.1f
#define BN_EPS 1e-5f

// problem dims
#define B_   16
#define CH   32
#define H0c  48
#define H2c  46
#define H3c  44
#define D0   2304
#define D1   2116
#define D2   1936
#define NF   512
#define BI   512
#define OC   1024
#define BOC  16384
#define NN2  (NF * NF)
#define OSL  (512 * D2)

// ---------------- scratch ----------------
__device__ float g_Sp[18 * NN2];        // VQ0 partials [0:9), DOT1 partials [9:18)
__device__ float g_Gp[18 * NN2];        // G partials (t*2+s); later reused for VQ1 (18 slices)
__device__ float g_h1[BI * D1];
__device__ float g_Cs[9 * NF * D2];     // shifted cb_fdw2; later reused for out partials (4 slices)
__device__ float g_A[BI * NF];
__device__ int   g_cnt[B_ * CH * NF];
__device__ int   g_idx0[BI];
__device__ int   g_idx1[BI];
__device__ int   g_idx2[BOC];
__device__ int   g_pair[NF * CH];
__device__ float g_qw1[CH * 9];
__device__ float g_qw2[CH * 9];
__device__ float g_qpw1[OC];
__device__ float g_qpw2[OC];
__device__ float g_nfdw[NF];
__device__ float g_nfpw[NF];
__device__ float g_nfdw2[NF];
__device__ float g_nfpw2[NF];

// ---------------- packed fp32x2 helpers ----------------
#define FMA2(acc, a, b) asm("fma.rn.f32x2 %0, %1, %2, %0;" : "+l"(acc) : "l"(a), "l"(b))
#define DUP2(d, x) asm("mov.b64 %0, {%1, %1};" : "=l"(d) : "r"(__float_as_uint(x)))

// ================= fused prep: shift_prep + norms + quantw =================
__global__ void prep_kernel(const float* __restrict__ cb_fdw, const float* __restrict__ cb_fpw,
                            const float* __restrict__ cb_fdw2, const float* __restrict__ cb_fpw2,
                            const float* __restrict__ dw1, const float* __restrict__ pw1,
                            const float* __restrict__ dw2, const float* __restrict__ pw2,
                            const float* __restrict__ cdw, const float* __restrict__ cpw,
                            const float* __restrict__ cdw2, const float* __restrict__ cpw2) {
    int b = blockIdx.x;
    if (b < 9 * NF) {
        int k = b & (NF - 1), t = b >> 9;
        int ty = t / 3, tx = t - ty * 3;
        const float* src = cb_fdw2 + (long)k * D1;
        float* dst = g_Cs + ((long)t * NF + k) * D2;
        for (int p = threadIdx.x; p < D2; p += 256) {
            int py = p / H3c, px = p - py * H3c;
            dst[p] = src[(py + ty) * H2c + px + tx];
        }
        return;
    }
    b -= 9 * NF;
    if (b < 4 * NF) {
        int row = b & (NF - 1), which = b >> 9;
        const float* src; int D; float* dst;
        if (which == 0)      { src = cb_fdw;  D = D0; dst = g_nfdw;  }
        else if (which == 1) { src = cb_fpw;  D = D1; dst = g_nfpw;  }
        else if (which == 2) { src = cb_fdw2; D = D1; dst = g_nfdw2; }
        else                 { src = cb_fpw2; D = D2; dst = g_nfpw2; }
        const float* p = src + (long)row * D;
        float s = 0.f;
        for (int i = threadIdx.x; i < D; i += 256) { float v = p[i]; s += v * v; }
        __shared__ float sm[256];
        sm[threadIdx.x] = s; __syncthreads();
        for (int o = 128; o > 0; o >>= 1) {
            if (threadIdx.x < o) sm[threadIdx.x] += sm[threadIdx.x + o];
            __syncthreads();
        }
        if (threadIdx.x == 0) dst[row] = sm[0];
        return;
    }
    // weight VQ (one block)
    int t = threadIdx.x;
    if (t < 32) {
        float w[9];
        for (int j = 0; j < 9; j++) w[j] = dw1[t * 9 + j];
        float bd = 3.4e38f; int bk = 0;
        for (int k = 0; k < 256; k++) {
            float d = 0.f;
            for (int j = 0; j < 9; j++) { float e = w[j] - cdw[k * 9 + j]; d += e * e; }
            if (d < bd) { bd = d; bk = k; }
        }
        for (int j = 0; j < 9; j++) g_qw1[t * 9 + j] = cdw[bk * 9 + j];
        for (int j = 0; j < 9; j++) w[j] = dw2[t * 9 + j];
        bd = 3.4e38f; bk = 0;
        for (int k = 0; k < 256; k++) {
            float d = 0.f;
            for (int j = 0; j < 9; j++) { float e = w[j] - cdw2[k * 9 + j]; d += e * e; }
            if (d < bd) { bd = d; bk = k; }
        }
        for (int j = 0; j < 9; j++) g_qw2[t * 9 + j] = cdw2[bk * 9 + j];
    }
    for (int c = t; c < OC; c += 256) {
        float w = pw1[c]; float bd = 3.4e38f; int bk = 0;
        for (int k = 0; k < 256; k++) { float e = w - cpw[k]; float d = e * e; if (d < bd) { bd = d; bk = k; } }
        g_qpw1[c] = cpw[bk];
        w = pw2[c]; bd = 3.4e38f; bk = 0;
        for (int k = 0; k < 256; k++) { float e = w - cpw2[k]; float d = e * e; if (d < bd) { bd = d; bk = k; } }
        g_qpw2[c] = cpw2[bk];
    }
}

__device__ __forceinline__ float4 ld4_guard(const float* p, int k, int kend) {
    return (k < kend) ? *(const float4*)(p + k) : make_float4(0.f, 0.f, 0.f, 0.f);
}

// ============ NT GEMM core: 256x128 block tile, 16x(4 n-pairs) per thread, 1 CTA/SM ============
__device__ __forceinline__ void nt_core(const float* __restrict__ A, const float* __restrict__ B,
                                        float* __restrict__ C, int ldk, int kb, int kend) {
    __shared__ float As[2][16][256];   // 32KB
    __shared__ float Bs[2][16][128];   // 16KB
    int tid = threadIdx.x;
    int m0 = blockIdx.y * 256, n0 = blockIdx.x * 128;
    int lrow = tid >> 2;            // 0..63
    int lk = (tid & 3) * 4;         // 0,4,8,12
    int tx = tid & 15, ty = tid >> 4;

    const float* Ar0 = A + (long)(m0 + lrow) * ldk;
    const float* Ar1 = Ar0 + 64L * ldk;
    const float* Ar2 = Ar0 + 128L * ldk;
    const float* Ar3 = Ar0 + 192L * ldk;
    const float* Br0 = B + (long)(n0 + lrow) * ldk;
    const float* Br1 = Br0 + 64L * ldk;

    unsigned long long acc[16][4] = {};

    {
        float4 a0 = ld4_guard(Ar0, kb + lk, kend);
        float4 a1 = ld4_guard(Ar1, kb + lk, kend);
        float4 a2 = ld4_guard(Ar2, kb + lk, kend);
        float4 a3 = ld4_guard(Ar3, kb + lk, kend);
        float4 b0 = ld4_guard(Br0, kb + lk, kend);
        float4 b1 = ld4_guard(Br1, kb + lk, kend);
#pragma unroll
        for (int c = 0; c < 4; c++) {
            As[0][lk + c][lrow +   0] = ((const float*)&a0)[c];
            As[0][lk + c][lrow +  64] = ((const float*)&a1)[c];
            As[0][lk + c][lrow + 128] = ((const float*)&a2)[c];
            As[0][lk + c][lrow + 192] = ((const float*)&a3)[c];
            Bs[0][lk + c][lrow +   0] = ((const float*)&b0)[c];
            Bs[0][lk + c][lrow +  64] = ((const float*)&b1)[c];
        }
    }
    __syncthreads();

    int buf = 0;
    for (int k0 = kb; k0 < kend; k0 += 16) {
        bool nxt = (k0 + 16) < kend;
        float4 na0, na1, na2, na3, nb0, nb1;
        if (nxt) {
            int kn = k0 + 16 + lk;
            na0 = ld4_guard(Ar0, kn, kend);
            na1 = ld4_guard(Ar1, kn, kend);
            na2 = ld4_guard(Ar2, kn, kend);
            na3 = ld4_guard(Ar3, kn, kend);
            nb0 = ld4_guard(Br0, kn, kend);
            nb1 = ld4_guard(Br1, kn, kend);
        }
#pragma unroll
        for (int kk = 0; kk < 16; kk++) {
            float4 fa0 = *(const float4*)&As[buf][kk][ty * 8];
            float4 fa1 = *(const float4*)&As[buf][kk][ty * 8 + 4];
            float4 fa2 = *(const float4*)&As[buf][kk][128 + ty * 8];
            float4 fa3 = *(const float4*)&As[buf][kk][128 + ty * 8 + 4];
            ulonglong2 b01 = *(const ulonglong2*)&Bs[buf][kk][tx * 4];
            ulonglong2 b23 = *(const ulonglong2*)&Bs[buf][kk][64 + tx * 4];
            float ar[16] = { fa0.x, fa0.y, fa0.z, fa0.w, fa1.x, fa1.y, fa1.z, fa1.w,
                             fa2.x, fa2.y, fa2.z, fa2.w, fa3.x, fa3.y, fa3.z, fa3.w };
#pragma unroll
            for (int i = 0; i < 16; i++) {
                unsigned long long ap; DUP2(ap, ar[i]);
                FMA2(acc[i][0], ap, b01.x); FMA2(acc[i][1], ap, b01.y);
                FMA2(acc[i][2], ap, b23.x); FMA2(acc[i][3], ap, b23.y);
            }
        }
        if (nxt) {
            int bN = buf ^ 1;
#pragma unroll
            for (int c = 0; c < 4; c++) {
                As[bN][lk + c][lrow +   0] = ((const float*)&na0)[c];
                As[bN][lk + c][lrow +  64] = ((const float*)&na1)[c];
                As[bN][lk + c][lrow + 128] = ((const float*)&na2)[c];
                As[bN][lk + c][lrow + 192] = ((const float*)&na3)[c];
                Bs[bN][lk + c][lrow +   0] = ((const float*)&nb0)[c];
                Bs[bN][lk + c][lrow +  64] = ((const float*)&nb1)[c];
            }
            __syncthreads();
            buf = bN;
        }
    }

#pragma unroll
    for (int i = 0; i < 16; i++) {
        int m = m0 + (i < 8 ? ty * 8 + i : 128 + ty * 8 + (i - 8));
        float* Cr = C + (long)m * NF + n0;
        *(unsigned long long*)(Cr + tx * 4)          = acc[i][0];
        *(unsigned long long*)(Cr + tx * 4 + 2)      = acc[i][1];
        *(unsigned long long*)(Cr + 64 + tx * 4)     = acc[i][2];
        *(unsigned long long*)(Cr + 64 + tx * 4 + 2) = acc[i][3];
    }
}

// -------- mega-batched NT GEMM: VQ0 (9 splits) + DOT1 (9 splits) + G (9x2 splits) --------
__global__ void __launch_bounds__(256, 1) mega_gemm(
    const float* __restrict__ x, const float* __restrict__ cbfdw,
    const float* __restrict__ cbfpw, const float* __restrict__ cbfdw2,
    const float* __restrict__ Cs, const float* __restrict__ cbfpw2,
    float* __restrict__ Sp, float* __restrict__ Gp)
{
    int z = blockIdx.z;
    const float* A; const float* B; float* C; int K, kb, kend;
    if (z < 9) {
        A = x; B = cbfdw; K = D0; kb = z * 256; kend = kb + 256; C = Sp + (long)z * NN2;
    } else if (z < 18) {
        int s = z - 9;
        A = cbfpw; B = cbfdw2; K = D1; kb = s * 236; kend = min(D1, kb + 236);
        C = Sp + (long)z * NN2;
    } else {
        int zz = z - 18, t = zz >> 1, s = zz & 1;
        A = Cs + (long)t * NF * D2; B = cbfpw2; K = D2;
        kb = s * 968; kend = kb + 968; C = Gp + (long)zz * NN2;
    }
    nt_core(A, B, C, K, kb, kend);
}

// -------- standalone NT GEMM (VQ1), split-K over z --------
__global__ void __launch_bounds__(256, 1) sgemm_nt(
    const float* __restrict__ A, const float* __restrict__ B, float* __restrict__ C,
    int K, int Kchunk)
{
    int s = blockIdx.z;
    int kb = s * Kchunk;
    int kend = min(K, kb + Kchunk);
    nt_core(A, B, C + (long)s * NN2, K, kb, kend);
}

// -------- out GEMM: partial C = A (512x512 chunk) * B (512x1936), split-K 4 --------
__global__ void __launch_bounds__(256) sgemm_nn_split(
    const float* __restrict__ A, const float* __restrict__ B, float* __restrict__ C)
{
    const int N = D2, K = NF;
    int kb = blockIdx.z * 128, kend = kb + 128;
    C += (long)blockIdx.z * OSL;

    __shared__ float As[2][16][128];
    __shared__ float Bs[2][16][128];

    int tid = threadIdx.x;
    int m0 = blockIdx.y * 128, n0 = blockIdx.x * 128;
    int lr = tid >> 1, lc = (tid & 1) * 8;      // A loader
    int krow = tid >> 4, nb_ = (tid & 15) * 8;  // B loader
    int tx = tid & 15, ty = tid >> 4;

    const float* Ab = A + (long)(m0 + lr) * K;
    unsigned long long acc[8][4] = {};

    {
        float4 aL = *(const float4*)(Ab + kb + lc);
        float4 aH = *(const float4*)(Ab + kb + lc + 4);
        As[0][lc + 0][lr] = aL.x; As[0][lc + 1][lr] = aL.y; As[0][lc + 2][lr] = aL.z; As[0][lc + 3][lr] = aL.w;
        As[0][lc + 4][lr] = aH.x; As[0][lc + 5][lr] = aH.y; As[0][lc + 6][lr] = aH.z; As[0][lc + 7][lr] = aH.w;
        float4 bL = (n0 + nb_ < N) ? *(const float4*)(B + (long)(kb + krow) * N + n0 + nb_)
                                   : make_float4(0.f, 0.f, 0.f, 0.f);
        float4 bH = (n0 + nb_ + 4 < N) ? *(const float4*)(B + (long)(kb + krow) * N + n0 + nb_ + 4)
                                       : make_float4(0.f, 0.f, 0.f, 0.f);
        *(float4*)&Bs[0][krow][nb_] = bL;
        *(float4*)&Bs[0][krow][nb_ + 4] = bH;
    }
    __syncthreads();

    int buf = 0;
    for (int k0 = kb; k0 < kend; k0 += 16) {
        bool nxt = (k0 + 16) < kend;
        float4 naL, naH, nbL, nbH;
        if (nxt) {
            naL = *(const float4*)(Ab + k0 + 16 + lc);
            naH = *(const float4*)(Ab + k0 + 16 + lc + 4);
            nbL = (n0 + nb_ < N) ? *(const float4*)(B + (long)(k0 + 16 + krow) * N + n0 + nb_)
                                 : make_float4(0.f, 0.f, 0.f, 0.f);
            nbH = (n0 + nb_ + 4 < N) ? *(const float4*)(B + (long)(k0 + 16 + krow) * N + n0 + nb_ + 4)
                                     : make_float4(0.f, 0.f, 0.f, 0.f);
        }
#pragma unroll
        for (int kk = 0; kk < 16; kk++) {
            float4 a0 = *(const float4*)&As[buf][kk][ty * 4];
            float4 a1 = *(const float4*)&As[buf][kk][64 + ty * 4];
            ulonglong2 b01 = *(const ulonglong2*)&Bs[buf][kk][tx * 4];
            ulonglong2 b23 = *(const ulonglong2*)&Bs[buf][kk][64 + tx * 4];
            float ar[8] = { a0.x, a0.y, a0.z, a0.w, a1.x, a1.y, a1.z, a1.w };
#pragma unroll
            for (int i = 0; i < 8; i++) {
                unsigned long long ap; DUP2(ap, ar[i]);
                FMA2(acc[i][0], ap, b01.x); FMA2(acc[i][1], ap, b01.y);
                FMA2(acc[i][2], ap, b23.x); FMA2(acc[i][3], ap, b23.y);
            }
        }
        if (nxt) {
            int bN = buf ^ 1;
            As[bN][lc + 0][lr] = naL.x; As[bN][lc + 1][lr] = naL.y; As[bN][lc + 2][lr] = naL.z; As[bN][lc + 3][lr] = naL.w;
            As[bN][lc + 4][lr] = naH.x; As[bN][lc + 5][lr] = naH.y; As[bN][lc + 6][lr] = naH.z; As[bN][lc + 7][lr] = naH.w;
            *(float4*)&Bs[bN][krow][nb_] = nbL;
            *(float4*)&Bs[bN][krow][nb_ + 4] = nbH;
            __syncthreads();
            buf = bN;
        }
    }

#pragma unroll
    for (int i = 0; i < 8; i++) {
        int m = m0 + (i < 4 ? ty * 4 + i : 64 + ty * 4 + i - 4);
        float* Cr = C + (long)m * N;
#pragma unroll
        for (int jp = 0; jp < 4; jp++) {
            int n = n0 + (jp < 2 ? tx * 4 + jp * 2 : 64 + tx * 4 + (jp - 2) * 2);
            if (n < N) *(unsigned long long*)(Cr + n) = acc[i][jp];
        }
    }
}

// ---------------- BN + lrelu reduce of 4 out partials ----------------
__global__ void bn_reduce(const float* __restrict__ P, float* __restrict__ out,
                          const float* __restrict__ gamma, const float* __restrict__ beta,
                          const float* __restrict__ rmean, const float* __restrict__ rvar) {
    int m = blockIdx.x;
    int g = m & 31;
    float sc = rsqrtf(rvar[g] + BN_EPS) * gamma[g];
    float mu = rmean[g], bt = beta[g];
    const float* p0 = P + (long)m * D2;
    float* o = out + (long)m * D2;
    for (int n = threadIdx.x; n < D2; n += 256) {
        float v = p0[n] + p0[n + OSL] + p0[n + 2 * OSL] + p0[n + 3 * OSL];
        v = (v - mu) * sc + bt;
        o[n] = (v >= 0.f) ? v : LEAK * v;
    }
}

// ---------------- row-wise argmin of (norms[k] - 2*sum_s Sp[s,row,k]) ----------------
__global__ void argmin_rows(const float* __restrict__ Sp, const float* __restrict__ norms,
                            int* __restrict__ out, int nsplit) {
    int row = blockIdx.x;
    float bd = 3.4e38f; int bk = 0;
    for (int k = threadIdx.x; k < NF; k += 256) {
        float s = 0.f;
        for (int sp = 0; sp < nsplit; sp++)
            s += Sp[((long)sp * NF + row) * NF + k];
        float d = norms[k] - 2.0f * s;
        if (d < bd) { bd = d; bk = k; }
    }
    __shared__ float sd[256]; __shared__ int si[256];
    sd[threadIdx.x] = bd; si[threadIdx.x] = bk; __syncthreads();
    for (int o = 128; o > 0; o >>= 1) {
        if (threadIdx.x < o) {
            float d2 = sd[threadIdx.x + o]; int k2 = si[threadIdx.x + o];
            if (d2 < sd[threadIdx.x] || (d2 == sd[threadIdx.x] && k2 < si[threadIdx.x])) {
                sd[threadIdx.x] = d2; si[threadIdx.x] = k2;
            }
        }
        __syncthreads();
    }
    if (threadIdx.x == 0) out[row] = si[0];
}

// ---------------- conv1 + lrelu ----------------
__global__ void conv1_lrelu(const float* __restrict__ cb_fdw) {
    int v = blockIdx.x;
    int i = v & 31;
    __shared__ float w[9];
    if (threadIdx.x < 9) w[threadIdx.x] = g_qw1[i * 9 + threadIdx.x];
    __syncthreads();
    const float* src = cb_fdw + (long)g_idx0[v] * D0;
    for (int p = threadIdx.x; p < D1; p += 256) {
        int py = p / H2c, px = p - py * H2c;
        const float* s0 = src + py * H0c + px;
        float acc = s0[0] * w[0] + s0[1] * w[1] + s0[2] * w[2]
                  + s0[H0c] * w[3] + s0[H0c + 1] * w[4] + s0[H0c + 2] * w[5]
                  + s0[2 * H0c] * w[6] + s0[2 * H0c + 1] * w[7] + s0[2 * H0c + 2] * w[8];
        g_h1[(long)v * D1 + p] = (acc >= 0.f) ? acc : LEAK * acc;
    }
}

// ---------------- idx2 ----------------
__global__ void idx2_kernel(const float* __restrict__ DOT, int nsplit) {
    int vbi = blockIdx.x;           // b*32 + i
    int b = vbi >> 5, i = vbi & 31;
    int j = g_idx1[vbi];
    __shared__ float dr[NF]; __shared__ float nn[NF];
    for (int k = threadIdx.x; k < NF; k += 256) {
        float v = 0.f;
        for (int sp = 0; sp < nsplit; sp++)
            v += DOT[((long)sp * NF + j) * NF + k];
        dr[k] = v;
        nn[k] = g_nfdw2[k];
    }
    __syncthreads();
    int warp = threadIdx.x >> 5, lane = threadIdx.x & 31;
    for (int o = warp; o < CH; o += 8) {
        float s = g_qpw1[o * 32 + i];
        float bd = 3.4e38f; int bk = 0;
        for (int k = lane; k < NF; k += 32) {
            float d = nn[k] - 2.0f * s * dr[k];
            if (d < bd) { bd = d; bk = k; }
        }
        for (int off = 16; off > 0; off >>= 1) {
            float d2 = __shfl_down_sync(0xffffffffu, bd, off);
            int k2 = __shfl_down_sync(0xffffffffu, bk, off);
            if (d2 < bd || (d2 == bd && k2 < bk)) { bd = d2; bk = k2; }
        }
        if (lane == 0) g_idx2[b * OC + o * 32 + i] = bk;
    }
}

// ---------------- pair argmin over m per (k,o) ----------------
__global__ void __launch_bounds__(256) pair_kernel(int nsplit) {
    int k = blockIdx.x;
    __shared__ float gs[9][NF];
    __shared__ float nn[NF];
    __shared__ float ws[CH * 9];
    for (int t = 0; t < 9; t++)
        for (int m = threadIdx.x; m < NF; m += 256) {
            float v = 0.f;
            for (int s = 0; s < nsplit; s++)
                v += g_Gp[((long)(t * nsplit + s) * NF + k) * NF + m];
            gs[t][m] = v;
        }
    for (int i = threadIdx.x; i < CH * 9; i += 256) ws[i] = g_qw2[i];
    for (int m = threadIdx.x; m < NF; m += 256) nn[m] = g_nfpw2[m];
    __syncthreads();
    int warp = threadIdx.x >> 5, lane = threadIdx.x & 31;
    for (int o = warp; o < CH; o += 8) {
        float wv[9];
#pragma unroll
        for (int t = 0; t < 9; t++) wv[t] = ws[o * 9 + t];
        float bd = 3.4e38f; int bk = 0;
        for (int m = lane; m < NF; m += 32) {
            float T = 0.f;
#pragma unroll
            for (int t = 0; t < 9; t++) T += wv[t] * gs[t][m];
            float d = nn[m] - 2.0f * T;
            if (d < bd) { bd = d; bk = m; }
        }
        for (int off = 16; off > 0; off >>= 1) {
            float d2 = __shfl_down_sync(0xffffffffu, bd, off);
            int k2 = __shfl_down_sync(0xffffffffu, bk, off);
            if (d2 < bd || (d2 == bd && k2 < bk)) { bd = d2; bk = k2; }
        }
        if (lane == 0) g_pair[k * CH + o] = bk;
    }
}

// ---------------- histogram ----------------
__global__ void cnt_kernel() {
    int bo = blockIdx.x;
    __shared__ int c[NF];
    for (int m = threadIdx.x; m < NF; m += 256) c[m] = 0;
    __syncthreads();
    if (threadIdx.x == 0) {
        int b = bo >> 5, o = bo & 31;
        for (int i = 0; i < 32; i++) {
            int k2 = g_idx2[b * OC + o * 32 + i];
            c[g_pair[k2 * CH + o]]++;
        }
    }
    __syncthreads();
    for (int m = threadIdx.x; m < NF; m += 256) g_cnt[(long)bo * NF + m] = c[m];
}

// ---------------- A[bg][m] = sum_o qpw2[g*32+o] * cnt[b][o][m] ----------------
__global__ void A_kernel() {
    int bg = blockIdx.x;
    int b = bg >> 5, g = bg & 31;
    __shared__ float w[32];
    if (threadIdx.x < 32) w[threadIdx.x] = g_qpw2[g * 32 + threadIdx.x];
    __syncthreads();
    for (int m = threadIdx.x; m < NF; m += 256) {
        float acc = 0.f;
#pragma unroll
        for (int o = 0; o < 32; o++)
            acc += w[o] * (float)g_cnt[((long)(b * 32 + o)) * NF + m];
        g_A[(long)bg * NF + m] = acc;
    }
}

extern "C" void kernel_launch(void* const* d_in, const int* in_sizes, int n_in,
                              void* d_out, int out_size) {
    const float* x       = (const float*)d_in[0];
    const float* dw_w1   = (const float*)d_in[1];
    const float* pw_w1   = (const float*)d_in[2];
    const float* dw_w2   = (const float*)d_in[3];
    const float* pw_w2   = (const float*)d_in[4];
    const float* cb_dw   = (const float*)d_in[5];
    const float* cb_pw   = (const float*)d_in[6];
    const float* cb_dw2  = (const float*)d_in[7];
    const float* cb_pw2  = (const float*)d_in[8];
    const float* cb_fdw  = (const float*)d_in[9];
    const float* cb_fpw  = (const float*)d_in[10];
    const float* cb_fdw2 = (const float*)d_in[11];
    const float* cb_fpw2 = (const float*)d_in[12];
    const float* gamma   = (const float*)d_in[13];
    const float* beta    = (const float*)d_in[14];
    const float* rmean   = (const float*)d_in[15];
    const float* rvar    = (const float*)d_in[16];
    float* out = (float*)d_out;

    float *pSp, *pGp, *ph1, *pCs, *pA, *pnfdw, *pnfpw;
    cudaGetSymbolAddress((void**)&pSp, g_Sp);
    cudaGetSymbolAddress((void**)&pGp, g_Gp);
    cudaGetSymbolAddress((void**)&ph1, g_h1);
    cudaGetSymbolAddress((void**)&pCs, g_Cs);
    cudaGetSymbolAddress((void**)&pA, g_A);
    cudaGetSymbolAddress((void**)&pnfdw, g_nfdw);
    cudaGetSymbolAddress((void**)&pnfpw, g_nfpw);
    int *pidx0, *pidx1;
    cudaGetSymbolAddress((void**)&pidx0, g_idx0);
    cudaGetSymbolAddress((void**)&pidx1, g_idx1);

    // fused prep: shift (4608) + norms (2048) + quantw (1)
    prep_kernel<<<9 * NF + 4 * NF + 1, 256>>>(cb_fdw, cb_fpw, cb_fdw2, cb_fpw2,
                                              dw_w1, pw_w1, dw_w2, pw_w2,
                                              cb_dw, cb_pw, cb_dw2, cb_pw2);

    // mega GEMM: VQ0 (z 0-8) + DOT1 (z 9-17) + G (z 18-35); 288 blocks, 1 CTA/SM
    mega_gemm<<<dim3(4, 2, 36), 256>>>(x, cb_fdw, cb_fpw, cb_fdw2, pCs, cb_fpw2, pSp, pGp);

    // VQ0 chain
    argmin_rows<<<BI, 256>>>(pSp, pnfdw, pidx0, 9);
    conv1_lrelu<<<BI, 256>>>(cb_fdw);

    // consume Gp (G partials) before VQ1 reuses the buffer
    pair_kernel<<<NF, 256>>>(2);

    // VQ1 (K=2116, 18 splits of 120) -> writes into Gp slices 0..17
    sgemm_nt<<<dim3(4, 2, 18), 256>>>(ph1, cb_fpw, pGp, D1, 120);
    argmin_rows<<<BI, 256>>>(pGp, pnfpw, pidx1, 18);

    // idx2 from DOT1 partials (Sp slices 9..17)
    idx2_kernel<<<BI, 256>>>(pSp + 9L * NN2, 9);

    // histogram -> A -> out GEMM (split-K 4, partials into Cs) -> BN reduce
    cnt_kernel<<<B_ * CH, 256>>>();
    A_kernel<<<BI, 256>>>();
    sgemm_nn_split<<<dim3(16, 4, 4), 256>>>(pA, cb_fpw2, pCs);
    bn_reduce<<<BI, 256>>>(pCs, out, gamma, beta, rmean, rvar);
}

// round 8
// speedup vs baseline: 1.0546x; 1.0546x over previous
#include <cuda_runtime.h>

#define LEAK   0.1f
#define BN_EPS 1e-5f

// problem dims
#define B_   16
#define CH   32
#define H0c  48
#define H2c  46
#define H3c  44
#define D0   2304
#define D1   2116
#define D2   1936
#define NF   512
#define BI   512
#define OC   1024
#define BOC  16384
#define NN2  (NF * NF)
#define OSL  (512 * D2)

// ---------------- scratch ----------------
__device__ float g_Sp[8 * NN2];         // VQ0 partials [0:4) (reused by VQ1), DOT1 partials [4:8)
__device__ float g_Gp[27 * NN2];        // G partials (t*3+s)
__device__ float g_h1[BI * D1];
__device__ float g_Cs[9 * NF * D2];     // shifted cb_fdw2; later reused for out partials (2 slices)
__device__ float g_A[BI * NF];
__device__ int   g_cnt[B_ * CH * NF];
__device__ int   g_idx2[BOC];
__device__ int   g_pair[NF * CH];
__device__ float g_qw1[CH * 9];
__device__ float g_qw2[CH * 9];
__device__ float g_qpw1[OC];
__device__ float g_qpw2[OC];
__device__ float g_nfdw[NF];
__device__ float g_nfpw[NF];
__device__ float g_nfdw2[NF];
__device__ float g_nfpw2[NF];

// ---------------- packed fp32x2 helpers ----------------
#define FMA2(acc, a, b) asm("fma.rn.f32x2 %0, %1, %2, %0;" : "+l"(acc) : "l"(a), "l"(b))
#define DUP2(d, x) asm("mov.b64 %0, {%1, %1};" : "=l"(d) : "r"(__float_as_uint(x)))

// ================= fused prep: shift_prep + norms + quantw =================
__global__ void prep_kernel(const float* __restrict__ cb_fdw, const float* __restrict__ cb_fpw,
                            const float* __restrict__ cb_fdw2, const float* __restrict__ cb_fpw2,
                            const float* __restrict__ dw1, const float* __restrict__ pw1,
                            const float* __restrict__ dw2, const float* __restrict__ pw2,
                            const float* __restrict__ cdw, const float* __restrict__ cpw,
                            const float* __restrict__ cdw2, const float* __restrict__ cpw2) {
    int b = blockIdx.x;
    if (b < 9 * NF) {
        int k = b & (NF - 1), t = b >> 9;
        int ty = t / 3, tx = t - ty * 3;
        const float* src = cb_fdw2 + (long)k * D1;
        float* dst = g_Cs + ((long)t * NF + k) * D2;
        for (int p = threadIdx.x; p < D2; p += 256) {
            int py = p / H3c, px = p - py * H3c;
            dst[p] = src[(py + ty) * H2c + px + tx];
        }
        return;
    }
    b -= 9 * NF;
    if (b < 4 * NF) {
        int row = b & (NF - 1), which = b >> 9;
        const float* src; int D; float* dst;
        if (which == 0)      { src = cb_fdw;  D = D0; dst = g_nfdw;  }
        else if (which == 1) { src = cb_fpw;  D = D1; dst = g_nfpw;  }
        else if (which == 2) { src = cb_fdw2; D = D1; dst = g_nfdw2; }
        else                 { src = cb_fpw2; D = D2; dst = g_nfpw2; }
        const float* p = src + (long)row * D;
        float s = 0.f;
        for (int i = threadIdx.x; i < D; i += 256) { float v = p[i]; s += v * v; }
        __shared__ float sm[256];
        sm[threadIdx.x] = s; __syncthreads();
        for (int o = 128; o > 0; o >>= 1) {
            if (threadIdx.x < o) sm[threadIdx.x] += sm[threadIdx.x + o];
            __syncthreads();
        }
        if (threadIdx.x == 0) dst[row] = sm[0];
        return;
    }
    // weight VQ (one block)
    int t = threadIdx.x;
    if (t < 32) {
        float w[9];
        for (int j = 0; j < 9; j++) w[j] = dw1[t * 9 + j];
        float bd = 3.4e38f; int bk = 0;
        for (int k = 0; k < 256; k++) {
            float d = 0.f;
            for (int j = 0; j < 9; j++) { float e = w[j] - cdw[k * 9 + j]; d += e * e; }
            if (d < bd) { bd = d; bk = k; }
        }
        for (int j = 0; j < 9; j++) g_qw1[t * 9 + j] = cdw[bk * 9 + j];
        for (int j = 0; j < 9; j++) w[j] = dw2[t * 9 + j];
        bd = 3.4e38f; bk = 0;
        for (int k = 0; k < 256; k++) {
            float d = 0.f;
            for (int j = 0; j < 9; j++) { float e = w[j] - cdw2[k * 9 + j]; d += e * e; }
            if (d < bd) { bd = d; bk = k; }
        }
        for (int j = 0; j < 9; j++) g_qw2[t * 9 + j] = cdw2[bk * 9 + j];
    }
    for (int c = t; c < OC; c += 256) {
        float w = pw1[c]; float bd = 3.4e38f; int bk = 0;
        for (int k = 0; k < 256; k++) { float e = w - cpw[k]; float d = e * e; if (d < bd) { bd = d; bk = k; } }
        g_qpw1[c] = cpw[bk];
        w = pw2[c]; bd = 3.4e38f; bk = 0;
        for (int k = 0; k < 256; k++) { float e = w - cpw2[k]; float d = e * e; if (d < bd) { bd = d; bk = k; } }
        g_qpw2[c] = cpw2[bk];
    }
}

__device__ __forceinline__ float4 ld4_guard(const float* p, int k, int kend) {
    return (k < kend) ? *(const float4*)(p + k) : make_float4(0.f, 0.f, 0.f, 0.f);
}

// ================= NT GEMM core: compact A, direct-u64 B, K-step 16 (R6 best) =================
__device__ __forceinline__ void nt_core(const float* __restrict__ A, const float* __restrict__ B,
                                        float* __restrict__ C, int ldk, int kb, int kend) {
    __shared__ float As[2][16][128];
    __shared__ float Bs[2][16][128];
    int tid = threadIdx.x;
    int m0 = blockIdx.y * 128, n0 = blockIdx.x * 128;
    int lr = tid >> 1, lc = (tid & 1) * 8;
    int tx = tid & 15, ty = tid >> 4;

    const float* Ab = A + (long)(m0 + lr) * ldk;
    const float* Bb = B + (long)(n0 + lr) * ldk;

    unsigned long long acc[8][4] = {};

    {
        float4 aL = ld4_guard(Ab, kb + lc, kend);
        float4 aH = ld4_guard(Ab, kb + lc + 4, kend);
        float4 bL = ld4_guard(Bb, kb + lc, kend);
        float4 bH = ld4_guard(Bb, kb + lc + 4, kend);
        As[0][lc + 0][lr] = aL.x; As[0][lc + 1][lr] = aL.y; As[0][lc + 2][lr] = aL.z; As[0][lc + 3][lr] = aL.w;
        As[0][lc + 4][lr] = aH.x; As[0][lc + 5][lr] = aH.y; As[0][lc + 6][lr] = aH.z; As[0][lc + 7][lr] = aH.w;
        Bs[0][lc + 0][lr] = bL.x; Bs[0][lc + 1][lr] = bL.y; Bs[0][lc + 2][lr] = bL.z; Bs[0][lc + 3][lr] = bL.w;
        Bs[0][lc + 4][lr] = bH.x; Bs[0][lc + 5][lr] = bH.y; Bs[0][lc + 6][lr] = bH.z; Bs[0][lc + 7][lr] = bH.w;
    }
    __syncthreads();

    int buf = 0;
    for (int k0 = kb; k0 < kend; k0 += 16) {
        bool nxt = (k0 + 16) < kend;
        float4 naL, naH, nbL, nbH;
        if (nxt) {
            naL = ld4_guard(Ab, k0 + 16 + lc, kend);
            naH = ld4_guard(Ab, k0 + 16 + lc + 4, kend);
            nbL = ld4_guard(Bb, k0 + 16 + lc, kend);
            nbH = ld4_guard(Bb, k0 + 16 + lc + 4, kend);
        }
#pragma unroll
        for (int kk = 0; kk < 16; kk++) {
            float4 a0 = *(const float4*)&As[buf][kk][ty * 4];
            float4 a1 = *(const float4*)&As[buf][kk][64 + ty * 4];
            ulonglong2 b01 = *(const ulonglong2*)&Bs[buf][kk][tx * 4];
            ulonglong2 b23 = *(const ulonglong2*)&Bs[buf][kk][64 + tx * 4];
            float ar[8] = { a0.x, a0.y, a0.z, a0.w, a1.x, a1.y, a1.z, a1.w };
#pragma unroll
            for (int i = 0; i < 8; i++) {
                unsigned long long ap; DUP2(ap, ar[i]);
                FMA2(acc[i][0], ap, b01.x); FMA2(acc[i][1], ap, b01.y);
                FMA2(acc[i][2], ap, b23.x); FMA2(acc[i][3], ap, b23.y);
            }
        }
        if (nxt) {
            int bN = buf ^ 1;
            As[bN][lc + 0][lr] = naL.x; As[bN][lc + 1][lr] = naL.y; As[bN][lc + 2][lr] = naL.z; As[bN][lc + 3][lr] = naL.w;
            As[bN][lc + 4][lr] = naH.x; As[bN][lc + 5][lr] = naH.y; As[bN][lc + 6][lr] = naH.z; As[bN][lc + 7][lr] = naH.w;
            Bs[bN][lc + 0][lr] = nbL.x; Bs[bN][lc + 1][lr] = nbL.y; Bs[bN][lc + 2][lr] = nbL.z; Bs[bN][lc + 3][lr] = nbL.w;
            Bs[bN][lc + 4][lr] = nbH.x; Bs[bN][lc + 5][lr] = nbH.y; Bs[bN][lc + 6][lr] = nbH.z; Bs[bN][lc + 7][lr] = nbH.w;
            __syncthreads();
            buf = bN;
        }
    }

#pragma unroll
    for (int i = 0; i < 8; i++) {
        int m = m0 + (i < 4 ? ty * 4 + i : 64 + ty * 4 + i - 4);
        float* Cr = C + (long)m * NF + n0;
        *(unsigned long long*)(Cr + tx * 4)          = acc[i][0];
        *(unsigned long long*)(Cr + tx * 4 + 2)      = acc[i][1];
        *(unsigned long long*)(Cr + 64 + tx * 4)     = acc[i][2];
        *(unsigned long long*)(Cr + 64 + tx * 4 + 2) = acc[i][3];
    }
}

// -------- batched NT GEMM: z+zoff -> VQ0 (0-3) | DOT1 (4-7) | G (8-34) --------
__global__ void __launch_bounds__(256) mega_gemm(
    const float* __restrict__ x, const float* __restrict__ cbfdw,
    const float* __restrict__ cbfpw, const float* __restrict__ cbfdw2,
    const float* __restrict__ Cs, const float* __restrict__ cbfpw2,
    float* __restrict__ Sp, float* __restrict__ Gp, int zoff)
{
    int z = blockIdx.z + zoff;
    const float* A; const float* B; float* C; int K, kb, kend;
    if (z < 4) {
        A = x; B = cbfdw; K = D0; kb = z * 576; kend = kb + 576; C = Sp + (long)z * NN2;
    } else if (z < 8) {
        int s = z - 4;
        A = cbfpw; B = cbfdw2; K = D1; kb = s * 532; kend = min(D1, kb + 532); C = Sp + (long)z * NN2;
    } else {
        int zz = z - 8, t = zz / 3, s = zz - t * 3;
        A = Cs + (long)t * NF * D2; B = cbfpw2; K = D2;
        kb = s * 648; kend = min(D2, kb + 648); C = Gp + (long)zz * NN2;
    }
    nt_core(A, B, C, K, kb, kend);
}

// -------- standalone NT GEMM (VQ1), split-K over z, writes Sp slices --------
__global__ void __launch_bounds__(256) sgemm_nt(
    const float* __restrict__ A, const float* __restrict__ B, float* __restrict__ C,
    int K, int Kchunk)
{
    int s = blockIdx.z;
    int kb = s * Kchunk;
    int kend = min(K, kb + Kchunk);
    nt_core(A, B, C + (long)s * NN2, K, kb, kend);
}

// -------- out GEMM: partial C = A (512x512 chunk) * B (512x1936), split-K 2 --------
__global__ void __launch_bounds__(256) sgemm_nn_split(
    const float* __restrict__ A, const float* __restrict__ B, float* __restrict__ C)
{
    const int N = D2, K = NF;
    int kb = blockIdx.z * 256, kend = kb + 256;
    C += (long)blockIdx.z * OSL;

    __shared__ float As[2][16][128];
    __shared__ float Bs[2][16][128];

    int tid = threadIdx.x;
    int m0 = blockIdx.y * 128, n0 = blockIdx.x * 128;
    int lr = tid >> 1, lc = (tid & 1) * 8;
    int krow = tid >> 4, nb_ = (tid & 15) * 8;
    int tx = tid & 15, ty = tid >> 4;

    const float* Ab = A + (long)(m0 + lr) * K;
    unsigned long long acc[8][4] = {};

    {
        float4 aL = *(const float4*)(Ab + kb + lc);
        float4 aH = *(const float4*)(Ab + kb + lc + 4);
        As[0][lc + 0][lr] = aL.x; As[0][lc + 1][lr] = aL.y; As[0][lc + 2][lr] = aL.z; As[0][lc + 3][lr] = aL.w;
        As[0][lc + 4][lr] = aH.x; As[0][lc + 5][lr] = aH.y; As[0][lc + 6][lr] = aH.z; As[0][lc + 7][lr] = aH.w;
        float4 bL = (n0 + nb_ < N) ? *(const float4*)(B + (long)(kb + krow) * N + n0 + nb_)
                                   : make_float4(0.f, 0.f, 0.f, 0.f);
        float4 bH = (n0 + nb_ + 4 < N) ? *(const float4*)(B + (long)(kb + krow) * N + n0 + nb_ + 4)
                                       : make_float4(0.f, 0.f, 0.f, 0.f);
        *(float4*)&Bs[0][krow][nb_] = bL;
        *(float4*)&Bs[0][krow][nb_ + 4] = bH;
    }
    __syncthreads();

    int buf = 0;
    for (int k0 = kb; k0 < kend; k0 += 16) {
        bool nxt = (k0 + 16) < kend;
        float4 naL, naH, nbL, nbH;
        if (nxt) {
            naL = *(const float4*)(Ab + k0 + 16 + lc);
            naH = *(const float4*)(Ab + k0 + 16 + lc + 4);
            nbL = (n0 + nb_ < N) ? *(const float4*)(B + (long)(k0 + 16 + krow) * N + n0 + nb_)
                                 : make_float4(0.f, 0.f, 0.f, 0.f);
            nbH = (n0 + nb_ + 4 < N) ? *(const float4*)(B + (long)(k0 + 16 + krow) * N + n0 + nb_ + 4)
                                     : make_float4(0.f, 0.f, 0.f, 0.f);
        }
#pragma unroll
        for (int kk = 0; kk < 16; kk++) {
            float4 a0 = *(const float4*)&As[buf][kk][ty * 4];
            float4 a1 = *(const float4*)&As[buf][kk][64 + ty * 4];
            ulonglong2 b01 = *(const ulonglong2*)&Bs[buf][kk][tx * 4];
            ulonglong2 b23 = *(const ulonglong2*)&Bs[buf][kk][64 + tx * 4];
            float ar[8] = { a0.x, a0.y, a0.z, a0.w, a1.x, a1.y, a1.z, a1.w };
#pragma unroll
            for (int i = 0; i < 8; i++) {
                unsigned long long ap; DUP2(ap, ar[i]);
                FMA2(acc[i][0], ap, b01.x); FMA2(acc[i][1], ap, b01.y);
                FMA2(acc[i][2], ap, b23.x); FMA2(acc[i][3], ap, b23.y);
            }
        }
        if (nxt) {
            int bN = buf ^ 1;
            As[bN][lc + 0][lr] = naL.x; As[bN][lc + 1][lr] = naL.y; As[bN][lc + 2][lr] = naL.z; As[bN][lc + 3][lr] = naL.w;
            As[bN][lc + 4][lr] = naH.x; As[bN][lc + 5][lr] = naH.y; As[bN][lc + 6][lr] = naH.z; As[bN][lc + 7][lr] = naH.w;
            *(float4*)&Bs[bN][krow][nb_] = nbL;
            *(float4*)&Bs[bN][krow][nb_ + 4] = nbH;
            __syncthreads();
            buf = bN;
        }
    }

#pragma unroll
    for (int i = 0; i < 8; i++) {
        int m = m0 + (i < 4 ? ty * 4 + i : 64 + ty * 4 + i - 4);
        float* Cr = C + (long)m * N;
#pragma unroll
        for (int jp = 0; jp < 4; jp++) {
            int n = n0 + (jp < 2 ? tx * 4 + jp * 2 : 64 + tx * 4 + (jp - 2) * 2);
            if (n < N) *(unsigned long long*)(Cr + n) = acc[i][jp];
        }
    }
}

// ---------------- BN + lrelu reduce of 2 out partials ----------------
__global__ void bn_reduce(const float* __restrict__ P, float* __restrict__ out,
                          const float* __restrict__ gamma, const float* __restrict__ beta,
                          const float* __restrict__ rmean, const float* __restrict__ rvar) {
    int m = blockIdx.x;
    int g = m & 31;
    float sc = rsqrtf(rvar[g] + BN_EPS) * gamma[g];
    float mu = rmean[g], bt = beta[g];
    const float* p0 = P + (long)m * D2;
    float* o = out + (long)m * D2;
    for (int n = threadIdx.x; n < D2; n += 256) {
        float v = p0[n] + p0[n + OSL];
        v = (v - mu) * sc + bt;
        o[n] = (v >= 0.f) ? v : LEAK * v;
    }
}

// ============ fused argmin(VQ0) + conv1 + lrelu: one block per v ============
__global__ void am0_conv1(const float* __restrict__ Sp, const float* __restrict__ cb_fdw) {
    int v = blockIdx.x;
    int i = v & 31;
    __shared__ float sd[256]; __shared__ int si[256];
    __shared__ float w[9];
    __shared__ int s_idx;
    if (threadIdx.x < 9) w[threadIdx.x] = g_qw1[i * 9 + threadIdx.x];
    float bd = 3.4e38f; int bk = 0;
    for (int k = threadIdx.x; k < NF; k += 256) {
        float s = 0.f;
#pragma unroll
        for (int sp = 0; sp < 4; sp++)
            s += Sp[((long)sp * NF + v) * NF + k];
        float d = g_nfdw[k] - 2.0f * s;
        if (d < bd) { bd = d; bk = k; }
    }
    sd[threadIdx.x] = bd; si[threadIdx.x] = bk; __syncthreads();
    for (int o = 128; o > 0; o >>= 1) {
        if (threadIdx.x < o) {
            float d2 = sd[threadIdx.x + o]; int k2 = si[threadIdx.x + o];
            if (d2 < sd[threadIdx.x] || (d2 == sd[threadIdx.x] && k2 < si[threadIdx.x])) {
                sd[threadIdx.x] = d2; si[threadIdx.x] = k2;
            }
        }
        __syncthreads();
    }
    if (threadIdx.x == 0) s_idx = si[0];
    __syncthreads();
    const float* src = cb_fdw + (long)s_idx * D0;
    for (int p = threadIdx.x; p < D1; p += 256) {
        int py = p / H2c, px = p - py * H2c;
        const float* s0 = src + py * H0c + px;
        float acc = s0[0] * w[0] + s0[1] * w[1] + s0[2] * w[2]
                  + s0[H0c] * w[3] + s0[H0c + 1] * w[4] + s0[H0c + 2] * w[5]
                  + s0[2 * H0c] * w[6] + s0[2 * H0c + 1] * w[7] + s0[2 * H0c + 2] * w[8];
        g_h1[(long)v * D1 + p] = (acc >= 0.f) ? acc : LEAK * acc;
    }
}

// ============ fused argmin(VQ1) + idx2 scan: one block per (b,i) ============
__global__ void am1_idx2(const float* __restrict__ Vp, const float* __restrict__ DOT) {
    int vbi = blockIdx.x;
    int b = vbi >> 5, i = vbi & 31;
    __shared__ float sd[256]; __shared__ int si[256];
    __shared__ int s_j;
    // phase 1: argmin over VQ1 row vbi (4 split partials)
    float bd = 3.4e38f; int bk = 0;
    for (int k = threadIdx.x; k < NF; k += 256) {
        float s = 0.f;
#pragma unroll
        for (int sp = 0; sp < 4; sp++)
            s += Vp[((long)sp * NF + vbi) * NF + k];
        float d = g_nfpw[k] - 2.0f * s;
        if (d < bd) { bd = d; bk = k; }
    }
    sd[threadIdx.x] = bd; si[threadIdx.x] = bk; __syncthreads();
    for (int o = 128; o > 0; o >>= 1) {
        if (threadIdx.x < o) {
            float d2 = sd[threadIdx.x + o]; int k2 = si[threadIdx.x + o];
            if (d2 < sd[threadIdx.x] || (d2 == sd[threadIdx.x] && k2 < si[threadIdx.x])) {
                sd[threadIdx.x] = d2; si[threadIdx.x] = k2;
            }
        }
        __syncthreads();
    }
    if (threadIdx.x == 0) s_j = si[0];
    __syncthreads();
    int j = s_j;
    // phase 2: per-o scaled argmin over DOT1 row j
    __shared__ float dr[NF]; __shared__ float nn[NF];
    for (int k = threadIdx.x; k < NF; k += 256) {
        float v = 0.f;
#pragma unroll
        for (int sp = 0; sp < 4; sp++)
            v += DOT[((long)sp * NF + j) * NF + k];
        dr[k] = v;
        nn[k] = g_nfdw2[k];
    }
    __syncthreads();
    int warp = threadIdx.x >> 5, lane = threadIdx.x & 31;
    for (int o = warp; o < CH; o += 8) {
        float s = g_qpw1[o * 32 + i];
        float bd2 = 3.4e38f; int bk2 = 0;
        for (int k = lane; k < NF; k += 32) {
            float d = nn[k] - 2.0f * s * dr[k];
            if (d < bd2) { bd2 = d; bk2 = k; }
        }
        for (int off = 16; off > 0; off >>= 1) {
            float d2 = __shfl_down_sync(0xffffffffu, bd2, off);
            int k2 = __shfl_down_sync(0xffffffffu, bk2, off);
            if (d2 < bd2 || (d2 == bd2 && k2 < bk2)) { bd2 = d2; bk2 = k2; }
        }
        if (lane == 0) g_idx2[b * OC + o * 32 + i] = bk2;
    }
}

// ---------------- pair argmin over m per (k,o) ----------------
__global__ void __launch_bounds__(256) pair_kernel(int nsplit) {
    int k = blockIdx.x;
    __shared__ float gs[9][NF];
    __shared__ float nn[NF];
    __shared__ float ws[CH * 9];
    for (int t = 0; t < 9; t++)
        for (int m = threadIdx.x; m < NF; m += 256) {
            float v = 0.f;
            for (int s = 0; s < nsplit; s++)
                v += g_Gp[((long)(t * nsplit + s) * NF + k) * NF + m];
            gs[t][m] = v;
        }
    for (int i = threadIdx.x; i < CH * 9; i += 256) ws[i] = g_qw2[i];
    for (int m = threadIdx.x; m < NF; m += 256) nn[m] = g_nfpw2[m];
    __syncthreads();
    int warp = threadIdx.x >> 5, lane = threadIdx.x & 31;
    for (int o = warp; o < CH; o += 8) {
        float wv[9];
#pragma unroll
        for (int t = 0; t < 9; t++) wv[t] = ws[o * 9 + t];
        float bd = 3.4e38f; int bk = 0;
        for (int m = lane; m < NF; m += 32) {
            float T = 0.f;
#pragma unroll
            for (int t = 0; t < 9; t++) T += wv[t] * gs[t][m];
            float d = nn[m] - 2.0f * T;
            if (d < bd) { bd = d; bk = m; }
        }
        for (int off = 16; off > 0; off >>= 1) {
            float d2 = __shfl_down_sync(0xffffffffu, bd, off);
            int k2 = __shfl_down_sync(0xffffffffu, bk, off);
            if (d2 < bd || (d2 == bd && k2 < bk)) { bd = d2; bk = k2; }
        }
        if (lane == 0) g_pair[k * CH + o] = bk;
    }
}

// ---------------- histogram ----------------
__global__ void cnt_kernel() {
    int bo = blockIdx.x;
    __shared__ int c[NF];
    for (int m = threadIdx.x; m < NF; m += 256) c[m] = 0;
    __syncthreads();
    if (threadIdx.x == 0) {
        int b = bo >> 5, o = bo & 31;
        for (int i = 0; i < 32; i++) {
            int k2 = g_idx2[b * OC + o * 32 + i];
            c[g_pair[k2 * CH + o]]++;
        }
    }
    __syncthreads();
    for (int m = threadIdx.x; m < NF; m += 256) g_cnt[(long)bo * NF + m] = c[m];
}

// ---------------- A[bg][m] = sum_o qpw2[g*32+o] * cnt[b][o][m] ----------------
__global__ void A_kernel() {
    int bg = blockIdx.x;
    int b = bg >> 5, g = bg & 31;
    __shared__ float w[32];
    if (threadIdx.x < 32) w[threadIdx.x] = g_qpw2[g * 32 + threadIdx.x];
    __syncthreads();
    for (int m = threadIdx.x; m < NF; m += 256) {
        float acc = 0.f;
#pragma unroll
        for (int o = 0; o < 32; o++)
            acc += w[o] * (float)g_cnt[((long)(b * 32 + o)) * NF + m];
        g_A[(long)bg * NF + m] = acc;
    }
}

extern "C" void kernel_launch(void* const* d_in, const int* in_sizes, int n_in,
                              void* d_out, int out_size) {
    const float* x       = (const float*)d_in[0];
    const float* dw_w1   = (const float*)d_in[1];
    const float* pw_w1   = (const float*)d_in[2];
    const float* dw_w2   = (const float*)d_in[3];
    const float* pw_w2   = (const float*)d_in[4];
    const float* cb_dw   = (const float*)d_in[5];
    const float* cb_pw   = (const float*)d_in[6];
    const float* cb_dw2  = (const float*)d_in[7];
    const float* cb_pw2  = (const float*)d_in[8];
    const float* cb_fdw  = (const float*)d_in[9];
    const float* cb_fpw  = (const float*)d_in[10];
    const float* cb_fdw2 = (const float*)d_in[11];
    const float* cb_fpw2 = (const float*)d_in[12];
    const float* gamma   = (const float*)d_in[13];
    const float* beta    = (const float*)d_in[14];
    const float* rmean   = (const float*)d_in[15];
    const float* rvar    = (const float*)d_in[16];
    float* out = (float*)d_out;

    float *pSp, *pGp, *ph1, *pCs, *pA;
    cudaGetSymbolAddress((void**)&pSp, g_Sp);
    cudaGetSymbolAddress((void**)&pGp, g_Gp);
    cudaGetSymbolAddress((void**)&ph1, g_h1);
    cudaGetSymbolAddress((void**)&pCs, g_Cs);
    cudaGetSymbolAddress((void**)&pA, g_A);

    // one-time aux stream + events (host objects only; no device allocations)
    static cudaStream_t s1 = [] { cudaStream_t s; cudaStreamCreateWithFlags(&s, cudaStreamNonBlocking); return s; }();
    static cudaEvent_t eFork = [] { cudaEvent_t e; cudaEventCreateWithFlags(&e, cudaEventDisableTiming); return e; }();
    static cudaEvent_t ePrep = [] { cudaEvent_t e; cudaEventCreateWithFlags(&e, cudaEventDisableTiming); return e; }();
    static cudaEvent_t eDot  = [] { cudaEvent_t e; cudaEventCreateWithFlags(&e, cudaEventDisableTiming); return e; }();
    static cudaEvent_t ePair = [] { cudaEvent_t e; cudaEventCreateWithFlags(&e, cudaEventDisableTiming); return e; }();

    // fork aux stream off the capture (default) stream
    cudaEventRecord(eFork, 0);
    cudaStreamWaitEvent(s1, eFork, 0);

    // ---- aux chain: prep -> DOT1 -> G -> pair ----
    prep_kernel<<<9 * NF + 4 * NF + 1, 256, 0, s1>>>(cb_fdw, cb_fpw, cb_fdw2, cb_fpw2,
                                                     dw_w1, pw_w1, dw_w2, pw_w2,
                                                     cb_dw, cb_pw, cb_dw2, cb_pw2);
    cudaEventRecord(ePrep, s1);
    mega_gemm<<<dim3(4, 4, 4), 256, 0, s1>>>(x, cb_fdw, cb_fpw, cb_fdw2, pCs, cb_fpw2,
                                             pSp, pGp, 4);   // DOT1 -> Sp[4..7]
    cudaEventRecord(eDot, s1);
    mega_gemm<<<dim3(4, 4, 27), 256, 0, s1>>>(x, cb_fdw, cb_fpw, cb_fdw2, pCs, cb_fpw2,
                                              pSp, pGp, 8);  // G -> Gp[0..26]
    pair_kernel<<<NF, 256, 0, s1>>>(3);
    cudaEventRecord(ePair, s1);

    // ---- main chain ----
    mega_gemm<<<dim3(4, 4, 4), 256>>>(x, cb_fdw, cb_fpw, cb_fdw2, pCs, cb_fpw2,
                                      pSp, pGp, 0);          // VQ0 -> Sp[0..3]
    cudaStreamWaitEvent(0, ePrep, 0);                        // norms + qw1
    am0_conv1<<<BI, 256>>>(pSp, cb_fdw);
    sgemm_nt<<<dim3(4, 4, 4), 256>>>(ph1, cb_fpw, pSp, D1, 532);  // VQ1 -> Sp[0..3]
    cudaStreamWaitEvent(0, eDot, 0);                         // DOT1 partials ready
    am1_idx2<<<BI, 256>>>(pSp, pSp + 4L * NN2);
    cudaStreamWaitEvent(0, ePair, 0);                        // pair table ready (joins s1)
    cnt_kernel<<<B_ * CH, 256>>>();
    A_kernel<<<BI, 256>>>();
    sgemm_nn_split<<<dim3(16, 4, 2), 256>>>(pA, cb_fpw2, pCs);
    bn_reduce<<<BI, 256>>>(pCs, out, gamma, beta, rmean, rvar);
}